// round 1
// baseline (speedup 1.0000x reference)
#include <cuda_runtime.h>
#include <cuda_bf16.h>
#include <math.h>

// ---------------- problem constants ----------------
#define Vn 32000
#define En 1024
#define Tn 2048
#define Hn 16
#define Dh 64
#define Ln 4
#define FFn 4096
#define Bn 4
#define ROWS (Bn * Tn)          // 8192
#define NHEADTOK (ROWS * Hn)    // 131072

// ---------------- scratch (static device memory; no runtime alloc) -------
// layout in floats:
#define SZ_X   ((size_t)ROWS * En)               // 8,388,608
#define OFF_X  ((size_t)0)
#define OFF_Q  (OFF_X + SZ_X)
#define OFF_K  (OFF_Q + SZ_X)
#define OFF_V  (OFF_K + SZ_X)
#define OFF_O  (OFF_V + SZ_X)
#define OFF_FF (OFF_O + SZ_X)                    // size ROWS*FFn = 33,554,432
#define OFF_S  (OFF_FF + (size_t)ROWS * FFn)     // size B*H*T*T = 268,435,456 (also reused for logits scratch)
#define OFF_RL (OFF_S + (size_t)Bn * Hn * Tn * Tn)
#define TOTALF (OFF_RL + ROWS + 64)

__device__ float g_buf[TOTALF];
__device__ int   g_flags[2];   // [0] = 1 if idx/targets are int64, 0 if int32

// ---------------- dtype detection (int32 vs int64 token indices) ---------
__global__ void detect_kernel(const void* idxp) {
    __shared__ int bad;
    if (threadIdx.x == 0) bad = 0;
    __syncthreads();
    const long long* p = (const long long*)idxp;
    // only read 4096 int64 = 32KB: safe whether buffer is 8192 int32 or 8192 int64
    for (int i = threadIdx.x; i < ROWS / 2; i += blockDim.x) {
        long long v = p[i];
        if (v < 0 || v >= Vn) bad = 1;
    }
    __syncthreads();
    if (threadIdx.x == 0) g_flags[0] = bad ? 0 : 1;
}

__device__ __forceinline__ long long read_token(const void* p, int i) {
    if (g_flags[0]) return ((const long long*)p)[i];
    return (long long)((const int*)p)[i];
}

// ---------------- embedding --------------------------------------------
__global__ void embed_kernel(const void* idxp, const float* __restrict__ tok,
                             const float* __restrict__ pos, float* __restrict__ x) {
    int row = blockIdx.x;              // b*T + t
    int t = row % Tn;
    long long token = read_token(idxp, row);
    const float* te = tok + (size_t)token * En;
    const float* pe = pos + (size_t)t * En;
    float* xo = x + (size_t)row * En;
#pragma unroll
    for (int i = 0; i < En / 256; i++) {
        int c = threadIdx.x + i * 256;
        xo[c] = te[c] + pe[c];
    }
}

// ---------------- tiled SGEMM, C = alpha*(A @ B^T) + bias  (NT) ----------
// A: [M,K] lda   B: [N,K] ldb   C: [M,N] ldc.  Batched over z = z1*z2dim + z2.
#define BM 64
#define BN 64
#define BK 16

__global__ __launch_bounds__(256)
void sgemm_nt(const float* __restrict__ A, const float* __restrict__ B,
              const float* __restrict__ bias, float* __restrict__ C,
              int M, int N, int K, int lda, int ldb, int ldc,
              int z2dim,
              long long sA1, long long sA2,
              long long sB1, long long sB2,
              long long sC1, long long sC2,
              float alpha, int fuse_gelu, int causal_skip)
{
    int bz = blockIdx.z;
    int z1 = bz / z2dim, z2 = bz - z1 * z2dim;
    A += z1 * sA1 + z2 * sA2;
    B += z1 * sB1 + z2 * sB2;
    C += z1 * sC1 + z2 * sC2;
    int m0 = blockIdx.y * BM, n0 = blockIdx.x * BN;
    if (causal_skip && n0 > m0 + BM - 1) return;   // strictly-upper tiles never read

    __shared__ float As[BK][BM];
    __shared__ float Bs[BK][BN];
    int tid = threadIdx.x;
    int tx = tid & 15, ty = tid >> 4;
    float acc[4][4] = {};

    for (int k0 = 0; k0 < K; k0 += BK) {
#pragma unroll
        for (int i = 0; i < 4; i++) {
            int idx = tid + i * 256;          // 0..1023
            int r = idx >> 4, kk = idx & 15;  // 16 k per row -> coalesced global reads
            As[kk][r] = A[(long long)(m0 + r) * lda + k0 + kk];
            Bs[kk][r] = B[(long long)(n0 + r) * ldb + k0 + kk];
        }
        __syncthreads();
#pragma unroll
        for (int kk = 0; kk < BK; kk++) {
            float4 a = *(const float4*)&As[kk][ty * 4];
            float4 b = *(const float4*)&Bs[kk][tx * 4];
            float av[4] = {a.x, a.y, a.z, a.w};
            float bv[4] = {b.x, b.y, b.z, b.w};
#pragma unroll
            for (int i = 0; i < 4; i++)
#pragma unroll
                for (int j = 0; j < 4; j++) acc[i][j] += av[i] * bv[j];
        }
        __syncthreads();
    }

#pragma unroll
    for (int i = 0; i < 4; i++) {
        long long m = m0 + ty * 4 + i;
#pragma unroll
        for (int j = 0; j < 4; j++) {
            int n = n0 + tx * 4 + j;
            float c = acc[i][j] * alpha;
            if (bias) c += bias[n];
            if (fuse_gelu) c = 0.5f * c * (1.0f + erff(c * 0.70710678118654752f));
            C[m * ldc + n] = c;
        }
    }
}

// ---------------- tiled SGEMM NN, C = A @ B (for attn @ V) ---------------
// A: [M,K] lda  B: [K,N] ldb  C: [M,N] ldc; causal_klimit caps K at m0+BM.
__global__ __launch_bounds__(256)
void sgemm_nn(const float* __restrict__ A, const float* __restrict__ B,
              float* __restrict__ C,
              int M, int N, int K, int lda, int ldb, int ldc,
              int z2dim,
              long long sA1, long long sA2,
              long long sB1, long long sB2,
              long long sC1, long long sC2,
              int causal_klimit)
{
    int bz = blockIdx.z;
    int z1 = bz / z2dim, z2 = bz - z1 * z2dim;
    A += z1 * sA1 + z2 * sA2;
    B += z1 * sB1 + z2 * sB2;
    C += z1 * sC1 + z2 * sC2;
    int m0 = blockIdx.y * BM, n0 = blockIdx.x * BN;
    int Keff = causal_klimit ? min(K, m0 + BM) : K;

    __shared__ float As[BK][BM];
    __shared__ float Bs[BK][BN];
    int tid = threadIdx.x;
    int tx = tid & 15, ty = tid >> 4;
    float acc[4][4] = {};

    for (int k0 = 0; k0 < Keff; k0 += BK) {
#pragma unroll
        for (int i = 0; i < 4; i++) {
            int idx = tid + i * 256;
            { int r = idx >> 4, kk = idx & 15;
              As[kk][r] = A[(long long)(m0 + r) * lda + k0 + kk]; }
            { int kk = idx >> 6, n = idx & 63;   // coalesced over n
              Bs[kk][n] = B[(long long)(k0 + kk) * ldb + n0 + n]; }
        }
        __syncthreads();
#pragma unroll
        for (int kk = 0; kk < BK; kk++) {
            float4 a = *(const float4*)&As[kk][ty * 4];
            float4 b = *(const float4*)&Bs[kk][tx * 4];
            float av[4] = {a.x, a.y, a.z, a.w};
            float bv[4] = {b.x, b.y, b.z, b.w};
#pragma unroll
            for (int i = 0; i < 4; i++)
#pragma unroll
                for (int j = 0; j < 4; j++) acc[i][j] += av[i] * bv[j];
        }
        __syncthreads();
    }

#pragma unroll
    for (int i = 0; i < 4; i++) {
        long long m = m0 + ty * 4 + i;
#pragma unroll
        for (int j = 0; j < 4; j++)
            C[m * ldc + n0 + tx * 4 + j] = acc[i][j];
    }
}

// ---------------- causal softmax over rows of S [BH, T, T] ---------------
__global__ void softmax_causal(float* __restrict__ S) {
    long long row = blockIdx.x;          // bh*T + i
    int i = (int)(row % Tn);
    float* p = S + row * (long long)Tn;
    int n = i + 1;
    int tid = threadIdx.x;
    __shared__ float red[256];

    float mx = -1e30f;
    for (int j = tid; j < n; j += 256) mx = fmaxf(mx, p[j]);
    red[tid] = mx; __syncthreads();
    for (int s = 128; s > 0; s >>= 1) { if (tid < s) red[tid] = fmaxf(red[tid], red[tid + s]); __syncthreads(); }
    mx = red[0]; __syncthreads();

    float sum = 0.f;
    for (int j = tid; j < n; j += 256) sum += expf(p[j] - mx);
    red[tid] = sum; __syncthreads();
    for (int s = 128; s > 0; s >>= 1) { if (tid < s) red[tid] += red[tid + s]; __syncthreads(); }
    float inv = 1.0f / red[0];

    for (int j = tid; j < n; j += 256) p[j] = expf(p[j] - mx) * inv;
    for (int j = n + tid; j < Tn; j += 256) p[j] = 0.f;
}

// ---------------- fused (a [+ res]) -> LayerNorm -------------------------
__global__ void add_layernorm(const float* __restrict__ a, const float* __restrict__ res,
                              const float* __restrict__ g, const float* __restrict__ b,
                              float* __restrict__ out)
{
    int row = blockIdx.x;
    const float* pa = a + (size_t)row * En;
    const float* pr = res ? res + (size_t)row * En : nullptr;
    float* po = out + (size_t)row * En;
    int tid = threadIdx.x;
    __shared__ float red[256];
    float v[En / 256];

    float s = 0.f;
#pragma unroll
    for (int i = 0; i < En / 256; i++) {
        int c = tid + i * 256;
        float x = pa[c] + (pr ? pr[c] : 0.f);
        v[i] = x; s += x;
    }
    red[tid] = s; __syncthreads();
    for (int st = 128; st > 0; st >>= 1) { if (tid < st) red[tid] += red[tid + st]; __syncthreads(); }
    float mean = red[0] * (1.0f / En); __syncthreads();

    float s2 = 0.f;
#pragma unroll
    for (int i = 0; i < En / 256; i++) { float d = v[i] - mean; s2 += d * d; }
    red[tid] = s2; __syncthreads();
    for (int st = 128; st > 0; st >>= 1) { if (tid < st) red[tid] += red[tid + st]; __syncthreads(); }
    float inv = rsqrtf(red[0] * (1.0f / En) + 1e-5f);

#pragma unroll
    for (int i = 0; i < En / 256; i++) {
        int c = tid + i * 256;
        po[c] = (v[i] - mean) * inv * g[c] + b[c];
    }
}

// ---------------- per-row loss: logsumexp - logit[target] ----------------
__global__ void loss_rows(const float* __restrict__ logits, const void* tgt,
                          float* __restrict__ rowloss)
{
    int r = blockIdx.x;
    const float* p = logits + (size_t)r * Vn;
    int tid = threadIdx.x;
    __shared__ float red[256];

    float mx = -1e30f;
    for (int j = tid; j < Vn; j += 256) mx = fmaxf(mx, p[j]);
    red[tid] = mx; __syncthreads();
    for (int s = 128; s > 0; s >>= 1) { if (tid < s) red[tid] = fmaxf(red[tid], red[tid + s]); __syncthreads(); }
    mx = red[0]; __syncthreads();

    float sum = 0.f;
    for (int j = tid; j < Vn; j += 256) sum += expf(p[j] - mx);
    red[tid] = sum; __syncthreads();
    for (int s = 128; s > 0; s >>= 1) { if (tid < s) red[tid] += red[tid + s]; __syncthreads(); }

    if (tid == 0) {
        long long t = read_token(tgt, r);
        rowloss[r] = logf(red[0]) + mx - p[t];
    }
}

__global__ void loss_reduce(const float* __restrict__ rowloss, float* __restrict__ out) {
    __shared__ float red[256];
    int tid = threadIdx.x;
    float s = 0.f;
    for (int i = tid; i < ROWS; i += 256) s += rowloss[i];
    red[tid] = s; __syncthreads();
    for (int st = 128; st > 0; st >>= 1) { if (tid < st) red[tid] += red[tid + st]; __syncthreads(); }
    if (tid == 0) out[0] = red[0] * (1.0f / ROWS);
}

// ---------------- host orchestration ------------------------------------
extern "C" void kernel_launch(void* const* d_in, const int* in_sizes, int n_in,
                              void* d_out, int out_size)
{
    const void*  idx     = d_in[0];
    const void*  tgt     = d_in[1];
    const float* tok_emb = (const float*)d_in[2];
    const float* pos_emb = (const float*)d_in[3];
    const float* Wq      = (const float*)d_in[4];
    const float* Wk      = (const float*)d_in[5];
    const float* Wv      = (const float*)d_in[6];
    const float* Wo      = (const float*)d_in[7];
    const float* bo      = (const float*)d_in[8];
    const float* ln1_g   = (const float*)d_in[9];
    const float* ln1_b   = (const float*)d_in[10];
    const float* W1      = (const float*)d_in[11];
    const float* b1      = (const float*)d_in[12];
    const float* W2      = (const float*)d_in[13];
    const float* b2      = (const float*)d_in[14];
    const float* ln2_g   = (const float*)d_in[15];
    const float* ln2_b   = (const float*)d_in[16];
    const float* lnf_g   = (const float*)d_in[17];
    const float* lnf_b   = (const float*)d_in[18];
    const float* lm_w    = (const float*)d_in[19];
    const float* lm_b    = (const float*)d_in[20];

    float* buf = nullptr;
    cudaGetSymbolAddress((void**)&buf, g_buf);
    float* X  = buf + OFF_X;
    float* Q  = buf + OFF_Q;
    float* Kb = buf + OFF_K;
    float* Vb = buf + OFF_V;
    float* O  = buf + OFF_O;
    float* FF = buf + OFF_FF;
    float* S  = buf + OFF_S;
    float* RL = buf + OFF_RL;

    const size_t NLOG = (size_t)ROWS * Vn;
    float* logits;
    long long loss_idx;
    if ((size_t)out_size >= NLOG + 1) { logits = (float*)d_out; loss_idx = (long long)NLOG; }
    else if ((size_t)out_size == NLOG) { logits = (float*)d_out; loss_idx = -1; }
    else { logits = S; loss_idx = 0; }   // loss-only output; use S scratch (free by then)

    detect_kernel<<<1, 256>>>(idx);
    embed_kernel<<<ROWS, 256>>>(idx, tok_emb, pos_emb, X);

    for (int l = 0; l < Ln; l++) {
        const float* wq = Wq + (size_t)l * Dh * Dh;
        const float* wk = Wk + (size_t)l * Dh * Dh;
        const float* wv = Wv + (size_t)l * Dh * Dh;
        const float* wo = Wo + (size_t)l * En * En;
        const float* w1 = W1 + (size_t)l * FFn * En;
        const float* w2 = W2 + (size_t)l * En * FFn;

        // q/k/v = xh @ W^T  : M = B*T*H rows of 64, N=K=64
        dim3 gp(1, NHEADTOK / BM, 1);
        sgemm_nt<<<gp, 256>>>(X, wq, nullptr, Q,  NHEADTOK, Dh, Dh, Dh, Dh, Dh,
                              1, 0, 0, 0, 0, 0, 0, 1.0f, 0, 0);
        sgemm_nt<<<gp, 256>>>(X, wk, nullptr, Kb, NHEADTOK, Dh, Dh, Dh, Dh, Dh,
                              1, 0, 0, 0, 0, 0, 0, 1.0f, 0, 0);
        sgemm_nt<<<gp, 256>>>(X, wv, nullptr, Vb, NHEADTOK, Dh, Dh, Dh, Dh, Dh,
                              1, 0, 0, 0, 0, 0, 0, 1.0f, 0, 0);

        // scores[bh] = Q K^T / 8  with causal tile skip
        dim3 gs(Tn / BN, Tn / BM, Bn * Hn);
        sgemm_nt<<<gs, 256>>>(Q, Kb, nullptr, S, Tn, Tn, Dh, En, En, Tn,
                              Hn,
                              (long long)Tn * En, (long long)Dh,
                              (long long)Tn * En, (long long)Dh,
                              (long long)Hn * Tn * Tn, (long long)Tn * Tn,
                              0.125f, 0, 1);

        softmax_causal<<<Bn * Hn * Tn, 256>>>(S);

        // O[bh] = S @ V, K capped causally per row-tile
        dim3 ga(1, Tn / BM, Bn * Hn);
        sgemm_nn<<<ga, 256>>>(S, Vb, O, Tn, Dh, Tn, Tn, En, En,
                              Hn,
                              (long long)Hn * Tn * Tn, (long long)Tn * Tn,
                              (long long)Tn * En, (long long)Dh,
                              (long long)Tn * En, (long long)Dh,
                              1);

        // attn proj: tmp(Q) = O @ Wo^T + bo
        dim3 go(En / BN, ROWS / BM, 1);
        sgemm_nt<<<go, 256>>>(O, wo, bo + (size_t)l * En, Q, ROWS, En, En, En, En, En,
                              1, 0, 0, 0, 0, 0, 0, 1.0f, 0, 0);
        add_layernorm<<<ROWS, 256>>>(Q, X, ln1_g + (size_t)l * En, ln1_b + (size_t)l * En, X);

        // FFN
        dim3 g1(FFn / BN, ROWS / BM, 1);
        sgemm_nt<<<g1, 256>>>(X, w1, b1 + (size_t)l * FFn, FF, ROWS, FFn, En, En, En, FFn,
                              1, 0, 0, 0, 0, 0, 0, 1.0f, 1, 0);  // fused exact GELU
        dim3 g2(En / BN, ROWS / BM, 1);
        sgemm_nt<<<g2, 256>>>(FF, w2, b2 + (size_t)l * En, Q, ROWS, En, FFn, FFn, FFn, En,
                              1, 0, 0, 0, 0, 0, 0, 1.0f, 0, 0);
        add_layernorm<<<ROWS, 256>>>(Q, X, ln2_g + (size_t)l * En, ln2_b + (size_t)l * En, X);
    }

    // final LN (in-place)
    add_layernorm<<<ROWS, 256>>>(X, nullptr, lnf_g, lnf_b, X);

    // LM head: logits = X @ lm_w^T + lm_b
    dim3 gl(Vn / BN, ROWS / BM, 1);
    sgemm_nt<<<gl, 256>>>(X, lm_w, lm_b, logits, ROWS, Vn, En, En, En, Vn,
                          1, 0, 0, 0, 0, 0, 0, 1.0f, 0, 0);

    // loss
    loss_rows<<<ROWS, 256>>>(logits, tgt, RL);
    if (loss_idx >= 0)
        loss_reduce<<<1, 256>>>(RL, ((float*)d_out) + loss_idx);
}

// round 7
// speedup vs baseline: 4.9998x; 4.9998x over previous
#include <cuda_runtime.h>
#include <cuda_bf16.h>
#include <math.h>
#include <cstdint>

// ---------------- problem constants ----------------
#define Vn 32000
#define En 1024
#define Tn 2048
#define Hn 16
#define Dh 64
#define Ln 4
#define FFn 4096
#define Bn 4
#define ROWS (Bn * Tn)          // 8192
#define NHEADTOK (ROWS * Hn)    // 131072

// ---------------- scratch (static device memory) -------------------------
#define SZ_X   ((size_t)ROWS * En)
#define OFF_X  ((size_t)0)
#define OFF_Q  (OFF_X + SZ_X)
#define OFF_K  (OFF_Q + SZ_X)
#define OFF_V  (OFF_K + SZ_X)
#define OFF_O  (OFF_V + SZ_X)
#define OFF_FF (OFF_O + SZ_X)                    // ROWS*FFn floats; reused as Vt during attention
#define OFF_S  (OFF_FF + (size_t)ROWS * FFn)
#define OFF_RL (OFF_S + (size_t)Bn * Hn * Tn * Tn)
#define TOTALF (OFF_RL + ROWS + 64)

__device__ float g_buf[TOTALF];
__device__ int   g_flags[2];

// =================== tf32 helpers (baseline PTX, no 'a' features) =========
__device__ __forceinline__ uint4 tf32x4(float4 v) {
    uint4 w;
    asm("cvt.rna.tf32.f32 %0, %1;" : "=r"(w.x) : "f"(v.x));
    asm("cvt.rna.tf32.f32 %0, %1;" : "=r"(w.y) : "f"(v.y));
    asm("cvt.rna.tf32.f32 %0, %1;" : "=r"(w.z) : "f"(v.z));
    asm("cvt.rna.tf32.f32 %0, %1;" : "=r"(w.w) : "f"(v.w));
    return w;
}

__device__ __forceinline__ void mma8(float c[4], const uint32_t a[4], const uint32_t b[2]) {
    asm volatile(
        "mma.sync.aligned.m16n8k8.row.col.f32.tf32.tf32.f32 "
        "{%0,%1,%2,%3}, {%4,%5,%6,%7}, {%8,%9}, {%0,%1,%2,%3};"
        : "+f"(c[0]), "+f"(c[1]), "+f"(c[2]), "+f"(c[3])
        : "r"(a[0]), "r"(a[1]), "r"(a[2]), "r"(a[3]), "r"(b[0]), "r"(b[1]));
}

// =================== warp-mma tf32 NT GEMM ================================
// C[M,N] = alpha*(A[M,K] @ B[N,K]^T) + bias, optional exact GELU.
// BM=128, BN in {64,128}, BK=16. 8 warps (4x2). Batched over z=z1*z2dim+z2.
// CAUSAL: 0 none, 1 skip tiles with n0>m0 (scores), 2 cap K at m0+128 (A*V).
template<int BN, int CAUSAL>
__global__ void __launch_bounds__(256)
mma_nt(const float* __restrict__ A, const float* __restrict__ B,
       const float* __restrict__ bias, float* __restrict__ C,
       int K, int lda, int ldb, int ldc,
       int z2dim,
       long long sA1, long long sA2, long long sB1, long long sB2,
       long long sC1, long long sC2,
       float alpha, int fuse_gelu)
{
    constexpr int BM = 128, BK = 16, SP = BK + 4;   // padded row stride (floats)
    constexpr int WN = BN / 2;                      // warp n-extent (4x2 warp grid)
    constexpr int NT = WN / 8;                      // n8 tiles per warp
    constexpr int NB = BN / 64;                     // B float4 loads per thread

    const int m0 = blockIdx.x * BM;
    const int n0 = blockIdx.y * BN;
    if (CAUSAL == 1 && n0 > m0) return;

    {
        int bz = blockIdx.z;
        int z1 = bz / z2dim, z2 = bz - z1 * z2dim;
        A += z1 * sA1 + z2 * sA2;
        B += z1 * sB1 + z2 * sB2;
        C += z1 * sC1 + z2 * sC2;
    }
    const int Keff = (CAUSAL == 2) ? min(K, m0 + BM) : K;

    __shared__ float As[2][BM * SP];
    __shared__ float Bs[2][BN * SP];

    const int tid = threadIdx.x;
    const int wid = tid >> 5, lane = tid & 31;
    const int wm = wid & 3, wn = wid >> 2;          // warp coords in 4x2
    const int grp = lane >> 2, tig = lane & 3;

    float acc[2][NT][4];
#pragma unroll
    for (int mt = 0; mt < 2; mt++)
#pragma unroll
        for (int nt = 0; nt < NT; nt++)
#pragma unroll
            for (int j = 0; j < 4; j++) acc[mt][nt][j] = 0.f;

    float4 aR[2], bR[NB];

    // ---- global load of one BK tile into registers ----
    auto load_tile = [&](int kt) {
        const int k0 = kt * BK;
#pragma unroll
        for (int i = 0; i < 2; i++) {
            int f = tid + i * 256;
            int r = f >> 2, c4 = (f & 3) * 4;
            aR[i] = *(const float4*)(A + (long long)(m0 + r) * lda + k0 + c4);
        }
#pragma unroll
        for (int i = 0; i < NB; i++) {
            int f = tid + i * 256;
            int r = f >> 2, c4 = (f & 3) * 4;
            bR[i] = *(const float4*)(B + (long long)(n0 + r) * ldb + k0 + c4);
        }
    };
    // ---- convert to tf32 and store to smem stage s ----
    auto store_tile = [&](int s) {
#pragma unroll
        for (int i = 0; i < 2; i++) {
            int f = tid + i * 256;
            int r = f >> 2, c4 = (f & 3) * 4;
            *(uint4*)&As[s][r * SP + c4] = tf32x4(aR[i]);
        }
#pragma unroll
        for (int i = 0; i < NB; i++) {
            int f = tid + i * 256;
            int r = f >> 2, c4 = (f & 3) * 4;
            *(uint4*)&Bs[s][r * SP + c4] = tf32x4(bR[i]);
        }
    };
    // ---- compute one BK tile from smem stage s ----
    auto compute = [&](int s) {
        const uint32_t* Au = (const uint32_t*)As[s];
        const uint32_t* Bu = (const uint32_t*)Bs[s];
#pragma unroll
        for (int ks = 0; ks < 2; ks++) {
            const int kb = ks * 8;
            uint32_t af[2][4];
#pragma unroll
            for (int mt = 0; mt < 2; mt++) {
                int row = wm * 32 + mt * 16;
                af[mt][0] = Au[(row + grp) * SP + kb + tig];
                af[mt][1] = Au[(row + grp + 8) * SP + kb + tig];
                af[mt][2] = Au[(row + grp) * SP + kb + tig + 4];
                af[mt][3] = Au[(row + grp + 8) * SP + kb + tig + 4];
            }
            uint32_t bf[NT][2];
#pragma unroll
            for (int nt = 0; nt < NT; nt++) {
                int col = wn * WN + nt * 8 + grp;
                bf[nt][0] = Bu[col * SP + kb + tig];
                bf[nt][1] = Bu[col * SP + kb + tig + 4];
            }
#pragma unroll
            for (int mt = 0; mt < 2; mt++)
#pragma unroll
                for (int nt = 0; nt < NT; nt++)
                    mma8(acc[mt][nt], af[mt], bf[nt]);
        }
    };

    const int nkt = Keff / BK;
    load_tile(0);
    store_tile(0);
    __syncthreads();
    for (int kt = 0; kt < nkt; kt++) {
        const int s = kt & 1;
        if (kt + 1 < nkt) load_tile(kt + 1);
        compute(s);
        if (kt + 1 < nkt) { store_tile(s ^ 1); __syncthreads(); }
    }

    // ---- epilogue ----
#pragma unroll
    for (int mt = 0; mt < 2; mt++) {
#pragma unroll
        for (int nt = 0; nt < NT; nt++) {
            const int col = n0 + wn * WN + nt * 8 + tig * 2;
            float b0 = bias ? bias[col] : 0.f;
            float b1 = bias ? bias[col + 1] : 0.f;
#pragma unroll
            for (int h = 0; h < 2; h++) {
                const long long row = m0 + wm * 32 + mt * 16 + grp + h * 8;
                float v0 = acc[mt][nt][h * 2 + 0] * alpha + b0;
                float v1 = acc[mt][nt][h * 2 + 1] * alpha + b1;
                if (fuse_gelu) {
                    v0 = 0.5f * v0 * (1.0f + erff(v0 * 0.70710678118654752f));
                    v1 = 0.5f * v1 * (1.0f + erff(v1 * 0.70710678118654752f));
                }
                *(float2*)(C + row * ldc + col) = make_float2(v0, v1);
            }
        }
    }
}

// =================== dtype detect / embed / LN / softmax / loss ===========
__global__ void detect_kernel(const void* idxp) {
    __shared__ int bad;
    if (threadIdx.x == 0) bad = 0;
    __syncthreads();
    const long long* p = (const long long*)idxp;
    for (int i = threadIdx.x; i < ROWS / 2; i += blockDim.x) {
        long long v = p[i];
        if (v < 0 || v >= Vn) bad = 1;
    }
    __syncthreads();
    if (threadIdx.x == 0) g_flags[0] = bad ? 0 : 1;
}

__device__ __forceinline__ long long read_token(const void* p, int i) {
    if (g_flags[0]) return ((const long long*)p)[i];
    return (long long)((const int*)p)[i];
}

__global__ void embed_kernel(const void* idxp, const float* __restrict__ tok,
                             const float* __restrict__ pos, float* __restrict__ x) {
    int row = blockIdx.x;
    int t = row % Tn;
    long long token = read_token(idxp, row);
    const float* te = tok + (size_t)token * En;
    const float* pe = pos + (size_t)t * En;
    float* xo = x + (size_t)row * En;
#pragma unroll
    for (int i = 0; i < En / 256; i++) {
        int c = threadIdx.x + i * 256;
        xo[c] = te[c] + pe[c];
    }
}

// V [B,T,H,Dh] -> Vt [B,H,Dh,T]
__global__ void transpose_v(const float* __restrict__ V, float* __restrict__ Vt) {
    __shared__ float tile[32][33];
    int bh = blockIdx.z;
    int b = bh / Hn, h = bh - b * Hn;
    int t0 = blockIdx.x * 32, d0 = blockIdx.y * 32;
    int tx = threadIdx.x, ty0 = threadIdx.y;
#pragma unroll
    for (int i = 0; i < 4; i++) {
        int ty = ty0 + i * 8;
        tile[ty][tx] = V[((size_t)(b * Tn + t0 + ty) * Hn + h) * Dh + d0 + tx];
    }
    __syncthreads();
#pragma unroll
    for (int i = 0; i < 4; i++) {
        int ty = ty0 + i * 8;
        Vt[((size_t)(b * Hn + h) * Dh + d0 + ty) * Tn + t0 + tx] = tile[tx][ty];
    }
}

__global__ void softmax_causal(float* __restrict__ S) {
    long long row = blockIdx.x;
    int i = (int)(row % Tn);
    float* p = S + row * (long long)Tn;
    int n = i + 1;
    int tid = threadIdx.x;
    __shared__ float red[256];

    float mx = -1e30f;
    for (int j = tid; j < n; j += 256) mx = fmaxf(mx, p[j]);
    red[tid] = mx; __syncthreads();
    for (int s = 128; s > 0; s >>= 1) { if (tid < s) red[tid] = fmaxf(red[tid], red[tid + s]); __syncthreads(); }
    mx = red[0]; __syncthreads();

    float sum = 0.f;
    for (int j = tid; j < n; j += 256) sum += expf(p[j] - mx);
    red[tid] = sum; __syncthreads();
    for (int s = 128; s > 0; s >>= 1) { if (tid < s) red[tid] += red[tid + s]; __syncthreads(); }
    float inv = 1.0f / red[0];

    for (int j = tid; j < n; j += 256) p[j] = expf(p[j] - mx) * inv;
    for (int j = n + tid; j < Tn; j += 256) p[j] = 0.f;
}

__global__ void add_layernorm(const float* __restrict__ a, const float* __restrict__ res,
                              const float* __restrict__ g, const float* __restrict__ b,
                              float* __restrict__ out)
{
    int row = blockIdx.x;
    const float* pa = a + (size_t)row * En;
    const float* pr = res ? res + (size_t)row * En : nullptr;
    float* po = out + (size_t)row * En;
    int tid = threadIdx.x;
    __shared__ float red[256];
    float v[En / 256];

    float s = 0.f;
#pragma unroll
    for (int i = 0; i < En / 256; i++) {
        int c = tid + i * 256;
        float x = pa[c] + (pr ? pr[c] : 0.f);
        v[i] = x; s += x;
    }
    red[tid] = s; __syncthreads();
    for (int st = 128; st > 0; st >>= 1) { if (tid < st) red[tid] += red[tid + st]; __syncthreads(); }
    float mean = red[0] * (1.0f / En); __syncthreads();

    float s2 = 0.f;
#pragma unroll
    for (int i = 0; i < En / 256; i++) { float d = v[i] - mean; s2 += d * d; }
    red[tid] = s2; __syncthreads();
    for (int st = 128; st > 0; st >>= 1) { if (tid < st) red[tid] += red[tid + st]; __syncthreads(); }
    float inv = rsqrtf(red[0] * (1.0f / En) + 1e-5f);

#pragma unroll
    for (int i = 0; i < En / 256; i++) {
        int c = tid + i * 256;
        po[c] = (v[i] - mean) * inv * g[c] + b[c];
    }
}

__global__ void loss_rows(const float* __restrict__ logits, const void* tgt,
                          float* __restrict__ rowloss)
{
    int r = blockIdx.x;
    const float* p = logits + (size_t)r * Vn;
    int tid = threadIdx.x;
    __shared__ float red[256];

    float mx = -1e30f;
    for (int j = tid; j < Vn; j += 256) mx = fmaxf(mx, p[j]);
    red[tid] = mx; __syncthreads();
    for (int s = 128; s > 0; s >>= 1) { if (tid < s) red[tid] = fmaxf(red[tid], red[tid + s]); __syncthreads(); }
    mx = red[0]; __syncthreads();

    float sum = 0.f;
    for (int j = tid; j < Vn; j += 256) sum += expf(p[j] - mx);
    red[tid] = sum; __syncthreads();
    for (int s = 128; s > 0; s >>= 1) { if (tid < s) red[tid] += red[tid + s]; __syncthreads(); }

    if (tid == 0) {
        long long t = read_token(tgt, r);
        rowloss[r] = logf(red[0]) + mx - p[t];
    }
}

__global__ void loss_reduce(const float* __restrict__ rowloss, float* __restrict__ out) {
    __shared__ float red[256];
    int tid = threadIdx.x;
    float s = 0.f;
    for (int i = tid; i < ROWS; i += 256) s += rowloss[i];
    red[tid] = s; __syncthreads();
    for (int st = 128; st > 0; st >>= 1) { if (tid < st) red[tid] += red[tid + st]; __syncthreads(); }
    if (tid == 0) out[0] = red[0] * (1.0f / ROWS);
}

// =================== host orchestration ===================================
extern "C" void kernel_launch(void* const* d_in, const int* in_sizes, int n_in,
                              void* d_out, int out_size)
{
    const void*  idx     = d_in[0];
    const void*  tgt     = d_in[1];
    const float* tok_emb = (const float*)d_in[2];
    const float* pos_emb = (const float*)d_in[3];
    const float* Wq      = (const float*)d_in[4];
    const float* Wk      = (const float*)d_in[5];
    const float* Wv      = (const float*)d_in[6];
    const float* Wo      = (const float*)d_in[7];
    const float* bo      = (const float*)d_in[8];
    const float* ln1_g   = (const float*)d_in[9];
    const float* ln1_b   = (const float*)d_in[10];
    const float* W1      = (const float*)d_in[11];
    const float* b1      = (const float*)d_in[12];
    const float* W2      = (const float*)d_in[13];
    const float* b2      = (const float*)d_in[14];
    const float* ln2_g   = (const float*)d_in[15];
    const float* ln2_b   = (const float*)d_in[16];
    const float* lnf_g   = (const float*)d_in[17];
    const float* lnf_b   = (const float*)d_in[18];
    const float* lm_w    = (const float*)d_in[19];
    const float* lm_b    = (const float*)d_in[20];

    float* buf = nullptr;
    cudaGetSymbolAddress((void**)&buf, g_buf);
    float* X  = buf + OFF_X;
    float* Q  = buf + OFF_Q;
    float* Kb = buf + OFF_K;
    float* Vb = buf + OFF_V;
    float* O  = buf + OFF_O;
    float* FF = buf + OFF_FF;     // also Vt scratch during attention
    float* Vt = FF;
    float* S  = buf + OFF_S;
    float* RL = buf + OFF_RL;

    const size_t NLOG = (size_t)ROWS * Vn;
    float* logits;
    long long loss_idx;
    if ((size_t)out_size >= NLOG + 1) { logits = (float*)d_out; loss_idx = (long long)NLOG; }
    else if ((size_t)out_size == NLOG) { logits = (float*)d_out; loss_idx = -1; }
    else { logits = S; loss_idx = 0; }

    detect_kernel<<<1, 256>>>(idx);
    embed_kernel<<<ROWS, 256>>>(idx, tok_emb, pos_emb, X);

    const long long TnE  = (long long)Tn * En;
    const long long TnTn = (long long)Tn * Tn;

    for (int l = 0; l < Ln; l++) {
        const float* wq = Wq + (size_t)l * Dh * Dh;
        const float* wk = Wk + (size_t)l * Dh * Dh;
        const float* wv = Wv + (size_t)l * Dh * Dh;
        const float* wo = Wo + (size_t)l * En * En;
        const float* w1 = W1 + (size_t)l * FFn * En;
        const float* w2 = W2 + (size_t)l * En * FFn;

        // q/k/v : [NHEADTOK,64] @ [64,64]^T
        dim3 gp(NHEADTOK / 128, 1, 1);
        mma_nt<64, 0><<<gp, 256>>>(X, wq, nullptr, Q,  Dh, Dh, Dh, Dh,
                                   1, 0, 0, 0, 0, 0, 0, 1.0f, 0);
        mma_nt<64, 0><<<gp, 256>>>(X, wk, nullptr, Kb, Dh, Dh, Dh, Dh,
                                   1, 0, 0, 0, 0, 0, 0, 1.0f, 0);
        mma_nt<64, 0><<<gp, 256>>>(X, wv, nullptr, Vb, Dh, Dh, Dh, Dh,
                                   1, 0, 0, 0, 0, 0, 0, 1.0f, 0);
        transpose_v<<<dim3(Tn / 32, 2, Bn * Hn), dim3(32, 8)>>>(Vb, Vt);

        // scores = Q K^T / 8  (lower+diag tiles only)
        mma_nt<128, 1><<<dim3(Tn / 128, Tn / 128, Bn * Hn), 256>>>(
            Q, Kb, nullptr, S, Dh, En, En, Tn,
            Hn, TnE, (long long)Dh, TnE, (long long)Dh,
            (long long)Hn * TnTn, TnTn, 0.125f, 0);

        softmax_causal<<<Bn * Hn * Tn, 256>>>(S);

        // O = S @ V = S @ Vt^T  (K capped causally per row tile)
        mma_nt<64, 2><<<dim3(Tn / 128, 1, Bn * Hn), 256>>>(
            S, Vt, nullptr, O, Tn, Tn, Tn, En,
            Hn, (long long)Hn * TnTn, TnTn,
            (long long)Hn * Dh * Tn, (long long)Dh * Tn,
            TnE, (long long)Dh, 1.0f, 0);

        // attn proj
        mma_nt<128, 0><<<dim3(ROWS / 128, En / 128, 1), 256>>>(
            O, wo, bo + (size_t)l * En, Q, En, En, En, En,
            1, 0, 0, 0, 0, 0, 0, 1.0f, 0);
        add_layernorm<<<ROWS, 256>>>(Q, X, ln1_g + (size_t)l * En, ln1_b + (size_t)l * En, X);

        // FFN
        mma_nt<128, 0><<<dim3(ROWS / 128, FFn / 128, 1), 256>>>(
            X, w1, b1 + (size_t)l * FFn, FF, En, En, En, FFn,
            1, 0, 0, 0, 0, 0, 0, 1.0f, 1);   // fused exact GELU
        mma_nt<128, 0><<<dim3(ROWS / 128, En / 128, 1), 256>>>(
            FF, w2, b2 + (size_t)l * En, Q, FFn, FFn, FFn, En,
            1, 0, 0, 0, 0, 0, 0, 1.0f, 0);
        add_layernorm<<<ROWS, 256>>>(Q, X, ln2_g + (size_t)l * En, ln2_b + (size_t)l * En, X);
    }

    add_layernorm<<<ROWS, 256>>>(X, nullptr, lnf_g, lnf_b, X);

    // LM head
    mma_nt<128, 0><<<dim3(ROWS / 128, Vn / 128, 1), 256>>>(
        X, lm_w, lm_b, logits, En, En, En, Vn,
        1, 0, 0, 0, 0, 0, 0, 1.0f, 0);

    loss_rows<<<ROWS, 256>>>(logits, tgt, RL);
    if (loss_idx >= 0)
        loss_reduce<<<1, 256>>>(RL, ((float*)d_out) + loss_idx);
}